// round 7
// baseline (speedup 1.0000x reference)
#include <cuda_runtime.h>
#include <cstdint>

// LoRA linear via rank-16 factor:
//   t   = x @ A^T   : [16384,4096] @ [4096,16] -> [16384,16]   (stage 1)
//   out = t @ B^T   : [16384,16]   @ [16,4096] -> [16384,4096] (stage 2)

#define D 4096
#define R 16
#define ROWS_TOTAL 16384
#define KC 32
#define NCH (D / KC)        // 128 chunks
#define ADS 18              // ad row stride in u64
#define AD_STAGE (16 * ADS)

typedef unsigned long long u64;

__device__ float g_t[ROWS_TOTAL * R];   // 1 MB scratch (fully overwritten)

__device__ __forceinline__ u64 fma2(u64 a, u64 b, u64 c) {
    u64 d; asm("fma.rn.f32x2 %0,%1,%2,%3;" : "=l"(d) : "l"(a), "l"(b), "l"(c)); return d;
}
__device__ __forceinline__ u64 pack2(float lo, float hi) {
    u64 d; asm("mov.b64 %0,{%1,%2};" : "=l"(d) : "f"(lo), "f"(hi)); return d;
}
__device__ __forceinline__ u64 dup2(float s) {
    u64 d; asm("mov.b64 %0,{%1,%1};" : "=l"(d) : "f"(s)); return d;
}
__device__ __forceinline__ float hsum2(u64 v) {
    float lo, hi; asm("mov.b64 {%0,%1},%2;" : "=f"(lo), "=f"(hi) : "l"(v)); return lo + hi;
}
__device__ __forceinline__ void cp16(uint32_t d, const void* s) {
    asm volatile("cp.async.cg.shared.global [%0],[%1],16;" :: "r"(d), "l"(s));
}
__device__ __forceinline__ void cpcommit() { asm volatile("cp.async.commit_group;"); }
__device__ __forceinline__ void cpwait2()  { asm volatile("cp.async.wait_group 2;"); }

// ---------------- Stage 1: t = x @ A^T ----------------
// Block 256 thr / 8 warps, 32 rows, grid 512, 3 CTAs/SM.
// Lane = (m = lane&15 -> rows 2m,2m+1 ; h = lane>>4 -> r in [8h, 8h+8)).
// Warp w owns k = w*4..w*4+3 (k-pairs 2w, 2w+1). f32x2 over (k-even,k-odd).
// acc: 2 rows x 8 r = 16 u64 (32 regs). One LDS.128 per row yields both
// k-pairs; A reads are 2-address (h split) broadcast LDS.128 = 1 phase.
// 4-stage cp.async ring, one __syncthreads per chunk, wait_group 2.
__global__ void __launch_bounds__(256, 3)
lora_stage1(const float* __restrict__ x, const float* __restrict__ A)
{
    __shared__ __align__(16) unsigned char sm[(16 + 10) * 1024];
    float* xs = (float*)sm;                  // [4][32 rows][32 k]  16 KB
    u64*   ad = (u64*)(sm + 16384);          // [4][16][ADS]        9.2 KB
    float* redf = (float*)sm;                // [8][32][16] overlay 16 KB

    const int tid  = threadIdx.x;
    const int w    = tid >> 5;
    const int lane = tid & 31;
    const int m    = lane & 15;
    const int h    = lane >> 4;
    const long rowBase = (long)blockIdx.x * 32;

    // x cp.async role: row = tid>>3 (0..31), slot s = tid&7 (k = 4s..4s+3)
    const int trow = tid >> 3, tslot = tid & 7;
    const int tphys = tslot ^ ((trow >> 1) & 7);
    const float* xsrc = x + (rowBase + trow) * D + tslot * 4;
    const uint32_t xs_sh = (uint32_t)__cvta_generic_to_shared(sm);
    const uint32_t xdst = xs_sh + (uint32_t)(trow * 128 + tphys * 16);

    // A role: r = tid>>4, kp = tid&15 (coalesced float2 per r-row)
    const int ar = tid >> 4, akp = tid & 15;
    const float* asrc = A + (long)ar * D + 2 * akp;

    // compute read addresses (within a stage)
    const int xphys = w ^ (m & 7);
    const float* xrd0 = xs + (2 * m) * 32 + xphys * 4;       // row 2m
    const float* xrd1 = xrd0 + 32;                            // row 2m+1

    u64 acc0[8], acc1[8];
    #pragma unroll
    for (int j = 0; j < 8; ++j) { acc0[j] = 0ULL; acc1[j] = 0ULL; }

    // ---- prologue: x chunks 0..2 in flight, A(0..1) staged, A(2) in regs ----
    #pragma unroll
    for (int cc = 0; cc < 3; ++cc) {
        cp16(xdst + (uint32_t)(cc * 4096), xsrc + cc * KC);
        cpcommit();
    }
    {
        float2 t0 = *(const float2*)(asrc);
        float2 t1 = *(const float2*)(asrc + KC);
        ad[0 * AD_STAGE + akp * ADS + ar] = pack2(t0.x, t0.y);
        ad[1 * AD_STAGE + akp * ADS + ar] = pack2(t1.x, t1.y);
    }
    float2 apf = *(const float2*)(asrc + 2 * KC);

    #pragma unroll 4
    for (int c = 0; c < NCH; ++c) {
        const int s = c & 3;
        cpwait2();           // chunk c landed (this thread's group)
        __syncthreads();     // visible to all + compute(c-1) done

        if (c + 3 < NCH)
            cp16(xdst + (uint32_t)(((c + 3) & 3) * 4096), xsrc + (c + 3) * KC);
        cpcommit();          // always: group count == chunk count

        if (c + 2 < NCH)
            ad[((c + 2) & 3) * AD_STAGE + akp * ADS + ar] = pack2(apf.x, apf.y);
        if (c + 3 < NCH)
            apf = *(const float2*)(asrc + (c + 3) * KC);

        // ---- compute chunk c ----
        ulonglong2 xa = *(const ulonglong2*)(xrd0 + s * 1024);   // row 2m, kp 2w/2w+1
        ulonglong2 ya = *(const ulonglong2*)(xrd1 + s * 1024);   // row 2m+1
        const u64* adbase = ad + s * AD_STAGE + h * 8;
        #pragma unroll
        for (int kp2 = 0; kp2 < 2; ++kp2) {
            const u64 xv = kp2 ? xa.y : xa.x;
            const u64 yv = kp2 ? ya.y : ya.x;
            const u64* adk = adbase + (2 * w + kp2) * ADS;
            #pragma unroll
            for (int jj = 0; jj < 4; ++jj) {
                ulonglong2 av = *(const ulonglong2*)(adk + 2 * jj);  // r = 8h+2jj,+1
                acc0[2 * jj]     = fma2(xv, av.x, acc0[2 * jj]);
                acc0[2 * jj + 1] = fma2(xv, av.y, acc0[2 * jj + 1]);
                acc1[2 * jj]     = fma2(yv, av.x, acc1[2 * jj]);
                acc1[2 * jj + 1] = fma2(yv, av.y, acc1[2 * jj + 1]);
            }
        }
    }

    // ---- cross-warp reduction (warps hold disjoint k partials) ----
    __syncthreads();   // done with xs -> overlay redf[w][row][r]
    #pragma unroll
    for (int j = 0; j < 8; ++j) {
        redf[w * 512 + (2 * m)     * 16 + h * 8 + j] = hsum2(acc0[j]);
        redf[w * 512 + (2 * m + 1) * 16 + h * 8 + j] = hsum2(acc1[j]);
    }
    __syncthreads();

    {
        const int e = 2 * tid;                 // 0..510, pair (e, e+1) same row
        const int row = e >> 4, r = e & 15;
        float s0 = 0.f, s1 = 0.f;
        #pragma unroll
        for (int ww = 0; ww < 8; ++ww) {
            s0 += redf[ww * 512 + row * 16 + r];
            s1 += redf[ww * 512 + row * 16 + r + 1];
        }
        *(float2*)(g_t + (rowBase + row) * R + r) = make_float2(s0, s1);
    }
}

// ---------------- Stage 2: out = t @ B^T ----------------
// Block 256 thr, tile 128 rows x 512 cols, 3 CTAs/SM.
// Thread owns col-pair (c0, c0+1); bpair[r] = (B[c0][r], B[c1][r]) in regs.
// t stored DUPLICATED in smem: tsd[row][r] = (t,t) -> fma2 accumulates both
// columns at once; result u64 stored directly (STG.64), no hsum.
__global__ void __launch_bounds__(256, 3)
lora_stage2(const float* __restrict__ B, float* __restrict__ out)
{
    __shared__ u64 tsd[128 * R];   // 16 KB

    const int tid = threadIdx.x;
    const long rowBase = (long)blockIdx.y * 128;
    const int c0 = blockIdx.x * 512 + tid * 2;

    // build duplicated t tile: 2048 scalars, 8 per thread
    {
        const float* tp = g_t + rowBase * R + tid * 8;
        float4 v0 = *(const float4*)(tp);
        float4 v1 = *(const float4*)(tp + 4);
        u64* dst = tsd + tid * 8;
        dst[0] = dup2(v0.x); dst[1] = dup2(v0.y);
        dst[2] = dup2(v0.z); dst[3] = dup2(v0.w);
        dst[4] = dup2(v1.x); dst[5] = dup2(v1.y);
        dst[6] = dup2(v1.z); dst[7] = dup2(v1.w);
    }

    // col-pair B in regs: bpair[r] = (B[c0][r], B[c1][r])
    u64 bp[16];
    {
        const float* b0 = B + (long)c0 * R;
        const float* b1 = b0 + R;
        float4 p0 = *(const float4*)(b0);
        float4 p1 = *(const float4*)(b0 + 4);
        float4 p2 = *(const float4*)(b0 + 8);
        float4 p3 = *(const float4*)(b0 + 12);
        float4 q0 = *(const float4*)(b1);
        float4 q1 = *(const float4*)(b1 + 4);
        float4 q2 = *(const float4*)(b1 + 8);
        float4 q3 = *(const float4*)(b1 + 12);
        bp[0]  = pack2(p0.x, q0.x); bp[1]  = pack2(p0.y, q0.y);
        bp[2]  = pack2(p0.z, q0.z); bp[3]  = pack2(p0.w, q0.w);
        bp[4]  = pack2(p1.x, q1.x); bp[5]  = pack2(p1.y, q1.y);
        bp[6]  = pack2(p1.z, q1.z); bp[7]  = pack2(p1.w, q1.w);
        bp[8]  = pack2(p2.x, q2.x); bp[9]  = pack2(p2.y, q2.y);
        bp[10] = pack2(p2.z, q2.z); bp[11] = pack2(p2.w, q2.w);
        bp[12] = pack2(p3.x, q3.x); bp[13] = pack2(p3.y, q3.y);
        bp[14] = pack2(p3.z, q3.z); bp[15] = pack2(p3.w, q3.w);
    }
    __syncthreads();

    float* orow = out + rowBase * (long)D + c0;
    #pragma unroll 2
    for (int row = 0; row < 128; ++row) {
        const u64* td = tsd + row * R;
        u64 acc = 0ULL;
        #pragma unroll
        for (int q = 0; q < 8; ++q) {
            ulonglong2 tv = *(const ulonglong2*)(td + 2 * q);   // broadcast
            acc = fma2(tv.x, bp[2 * q],     acc);
            acc = fma2(tv.y, bp[2 * q + 1], acc);
        }
        *(u64*)(orow + (long)row * D) = acc;   // (out[row][c0], out[row][c1])
    }
}

extern "C" void kernel_launch(void* const* d_in, const int* in_sizes, int n_in,
                              void* d_out, int out_size) {
    const float* x = (const float*)d_in[0];   // [16384, 4096]
    const float* A = (const float*)d_in[1];   // [16, 4096]
    const float* B = (const float*)d_in[2];   // [4096, 16]
    float* out = (float*)d_out;               // [16384, 4096]

    lora_stage1<<<ROWS_TOTAL / 32, 256>>>(x, A);
    dim3 g2(D / 512, ROWS_TOTAL / 128);
    lora_stage2<<<g2, 256>>>(B, out);
}

// round 8
// speedup vs baseline: 1.9525x; 1.9525x over previous
#include <cuda_runtime.h>
#include <cstdint>

// LoRA linear via rank-16 factor:
//   t   = x @ A^T   : [16384,4096] @ [4096,16] -> [16384,16]   (stage 1)
//   out = t @ B^T   : [16384,16]   @ [16,4096] -> [16384,4096] (stage 2)

#define D 4096
#define R 16
#define ROWS_TOTAL 16384
#define KC 64
#define NCH (D / KC)          // 64 chunks
#define ADS 18                // ad row stride in u64
#define AD_STAGE (32 * ADS)   // 32 k-pairs per chunk
#define XS_STAGE 4096         // floats per stage: 64 rows x 64 k
#define S1_SMEM (4 * XS_STAGE * 4 + 4 * AD_STAGE * 8)   // 65536 + 18432 = 83968

typedef unsigned long long u64;

__device__ float g_t[ROWS_TOTAL * R];   // 1 MB scratch (fully overwritten)

__device__ __forceinline__ u64 fma2(u64 a, u64 b, u64 c) {
    u64 d; asm("fma.rn.f32x2 %0,%1,%2,%3;" : "=l"(d) : "l"(a), "l"(b), "l"(c)); return d;
}
__device__ __forceinline__ u64 pack2(float lo, float hi) {
    u64 d; asm("mov.b64 %0,{%1,%2};" : "=l"(d) : "f"(lo), "f"(hi)); return d;
}
__device__ __forceinline__ float hsum2(u64 v) {
    float lo, hi; asm("mov.b64 {%0,%1},%2;" : "=f"(lo), "=f"(hi) : "l"(v)); return lo + hi;
}
__device__ __forceinline__ void cp16(uint32_t d, const void* s) {
    asm volatile("cp.async.cg.shared.global [%0],[%1],16;" :: "r"(d), "l"(s));
}
__device__ __forceinline__ void cpcommit() { asm volatile("cp.async.commit_group;"); }
__device__ __forceinline__ void cpwait2()  { asm volatile("cp.async.wait_group 2;"); }

// ---------------- Stage 1: t = x @ A^T ----------------
// R6-proven structure, KC doubled to 64 to halve per-chunk overhead.
// Block 256 thr / 8 warps, 64 rows, grid 256, 2 CTAs/SM (dynamic smem 82 KB).
// Lane l owns rows (2l, 2l+1); warp w owns k = w*8..w*8+7 (k-pairs 4w..4w+3).
// f32x2 packed over (k-even,k-odd); acc = 2 rows x 16 r = 32 u64.
// A pre-packed ad[kp][r] -> all A reads warp-broadcast LDS.128 (1 phase).
// x rows 64 floats, 16B-slot swizzle phys = slot ^ ((row>>1)&15) -> LDS.128
// reads hit all 8 bank groups (4-phase minimum, no extra conflicts).
// 4-stage cp.async ring, ONE __syncthreads per chunk, wait_group 2.
__global__ void __launch_bounds__(256, 2)
lora_stage1(const float* __restrict__ x, const float* __restrict__ A)
{
    extern __shared__ __align__(16) unsigned char sm[];
    float* xs = (float*)sm;                          // [4][64][64]  64 KB
    u64*   ad = (u64*)(sm + 4 * XS_STAGE * 4);       // [4][32][ADS] 18 KB
    float* redf = (float*)sm;                        // [8][64*17] overlay 34.8 KB

    const int tid  = threadIdx.x;
    const int w    = tid >> 5;
    const int lane = tid & 31;
    const long rowBase = (long)blockIdx.x * 64;

    // x cp.async role: row = tid>>2 (0..63), seg = tid&3 (16 floats = 4 slots)
    const int trow = tid >> 2, tseg = tid & 3;
    const int tswz = (trow >> 1) & 15;
    const float* xsrc = x + (rowBase + trow) * D;
    const uint32_t xs_sh = (uint32_t)__cvta_generic_to_shared(sm);
    const uint32_t xrow_sh = xs_sh + (uint32_t)trow * 256u;   // 64 floats/row

    // A role: r = tid>>4 (0..15), a16 = tid&15 -> k-pairs 2*a16, 2*a16+1
    const int ar = tid >> 4, a16 = tid & 15;
    const float* asrc = A + (long)ar * D + a16 * 4;

    // compute read constants: 16B slots (2w)^sw and (2w+1)^sw of rows 2l,2l+1
    const int sw = lane & 15;
    const int p0 = (2 * w) ^ sw;
    const int p1 = (2 * w + 1) ^ sw;
    const float* row0 = xs + (2 * lane) * 64;
    const float* row1 = row0 + 64;

    u64 acc0[16], acc1[16];
    #pragma unroll
    for (int r = 0; r < 16; ++r) { acc0[r] = 0ULL; acc1[r] = 0ULL; }

    // ---- prologue: x chunks 0..2 in flight, A(0..1) staged, A(2) in regs ----
    #pragma unroll
    for (int cc = 0; cc < 3; ++cc) {
        #pragma unroll
        for (int j = 0; j < 4; ++j) {
            const int slog = tseg * 4 + j;
            cp16(xrow_sh + (uint32_t)(cc * XS_STAGE * 4) + (uint32_t)((slog ^ tswz) * 16),
                 xsrc + cc * KC + slog * 4);
        }
        cpcommit();
    }
    {
        float4 t0 = *(const float4*)(asrc);
        float4 t1 = *(const float4*)(asrc + KC);
        ad[0 * AD_STAGE + (2 * a16) * ADS + ar]     = pack2(t0.x, t0.y);
        ad[0 * AD_STAGE + (2 * a16 + 1) * ADS + ar] = pack2(t0.z, t0.w);
        ad[1 * AD_STAGE + (2 * a16) * ADS + ar]     = pack2(t1.x, t1.y);
        ad[1 * AD_STAGE + (2 * a16 + 1) * ADS + ar] = pack2(t1.z, t1.w);
    }
    float4 apf = *(const float4*)(asrc + 2 * KC);

    for (int c = 0; c < NCH; ++c) {
        const int s = c & 3;
        cpwait2();           // chunk c landed (this thread's groups)
        __syncthreads();     // visible to all + compute(c-1) done

        if (c + 3 < NCH) {
            #pragma unroll
            for (int j = 0; j < 4; ++j) {
                const int slog = tseg * 4 + j;
                cp16(xrow_sh + (uint32_t)(((c + 3) & 3) * XS_STAGE * 4)
                             + (uint32_t)((slog ^ tswz) * 16),
                     xsrc + (c + 3) * KC + slog * 4);
            }
        }
        cpcommit();          // always: group count tracks chunk count

        if (c + 2 < NCH) {
            u64* adn = ad + ((c + 2) & 3) * AD_STAGE;
            adn[(2 * a16) * ADS + ar]     = pack2(apf.x, apf.y);
            adn[(2 * a16 + 1) * ADS + ar] = pack2(apf.z, apf.w);
        }
        if (c + 3 < NCH)
            apf = *(const float4*)(asrc + (c + 3) * KC);

        // ---- compute chunk c: k-pairs 4w..4w+3 ----
        const int xo = s * XS_STAGE;
        ulonglong2 xa0 = *(const ulonglong2*)(row0 + xo + p0 * 4);
        ulonglong2 xa1 = *(const ulonglong2*)(row0 + xo + p1 * 4);
        ulonglong2 ya0 = *(const ulonglong2*)(row1 + xo + p0 * 4);
        ulonglong2 ya1 = *(const ulonglong2*)(row1 + xo + p1 * 4);
        u64 xk[4] = { xa0.x, xa0.y, xa1.x, xa1.y };
        u64 yk[4] = { ya0.x, ya0.y, ya1.x, ya1.y };

        const u64* adc = ad + s * AD_STAGE;
        #pragma unroll
        for (int kp2 = 0; kp2 < 4; ++kp2) {
            const u64 xv = xk[kp2], yv = yk[kp2];
            const u64* adk = adc + (w * 4 + kp2) * ADS;
            #pragma unroll
            for (int rr = 0; rr < 8; ++rr) {
                ulonglong2 av = *(const ulonglong2*)(adk + 2 * rr);  // broadcast
                acc0[2 * rr]     = fma2(xv, av.x, acc0[2 * rr]);
                acc0[2 * rr + 1] = fma2(xv, av.y, acc0[2 * rr + 1]);
                acc1[2 * rr]     = fma2(yv, av.x, acc1[2 * rr]);
                acc1[2 * rr + 1] = fma2(yv, av.y, acc1[2 * rr + 1]);
            }
        }
    }

    // ---- cross-warp reduction (warps hold disjoint k partials) ----
    __syncthreads();   // done with xs/ad -> overlay redf
    #pragma unroll
    for (int r = 0; r < 16; ++r) {
        redf[w * 1088 + (2 * lane)     * 17 + r] = hsum2(acc0[r]);
        redf[w * 1088 + (2 * lane + 1) * 17 + r] = hsum2(acc1[r]);
    }
    __syncthreads();

    #pragma unroll
    for (int i = 0; i < 4; ++i) {
        const int e = tid + 256 * i;          // 0..1023
        const int row = e >> 4, r = e & 15;
        float s = 0.f;
        #pragma unroll
        for (int ww = 0; ww < 8; ++ww)
            s += redf[ww * 1088 + row * 17 + r];
        g_t[(rowBase + row) * R + r] = s;
    }
}

// ---------------- Stage 2: out = t @ B^T ---------------- (R6 known-good, ~56us)
__global__ void __launch_bounds__(256, 2)
lora_stage2(const float* __restrict__ B, float* __restrict__ out)
{
    __shared__ float ts[128 * R];   // 8 KB

    const int tid = threadIdx.x;
    const long rowBase = (long)blockIdx.y * 128;
    const int ob = blockIdx.x * 1024 + tid * 4;

    *(float4*)(ts + tid * 8)     = *(const float4*)(g_t + rowBase * R + tid * 8);
    *(float4*)(ts + tid * 8 + 4) = *(const float4*)(g_t + rowBase * R + tid * 8 + 4);

    u64 bb[4][8];
    #pragma unroll
    for (int j = 0; j < 4; ++j) {
        const float* bp = B + (long)(ob + j) * R;
        ulonglong2 v0 = *(const ulonglong2*)(bp);
        ulonglong2 v1 = *(const ulonglong2*)(bp + 4);
        ulonglong2 v2 = *(const ulonglong2*)(bp + 8);
        ulonglong2 v3 = *(const ulonglong2*)(bp + 12);
        bb[j][0] = v0.x; bb[j][1] = v0.y;
        bb[j][2] = v1.x; bb[j][3] = v1.y;
        bb[j][4] = v2.x; bb[j][5] = v2.y;
        bb[j][6] = v3.x; bb[j][7] = v3.y;
    }
    __syncthreads();

    for (int row = 0; row < 128; ++row) {
        u64 tt[8];
        #pragma unroll
        for (int q = 0; q < 4; ++q) {
            ulonglong2 v = *(const ulonglong2*)(ts + row * R + q * 4);
            tt[2 * q]     = v.x;
            tt[2 * q + 1] = v.y;
        }
        float res[4];
        #pragma unroll
        for (int j = 0; j < 4; ++j) {
            u64 a = 0ULL;
            #pragma unroll
            for (int p = 0; p < 8; ++p)
                a = fma2(bb[j][p], tt[p], a);
            res[j] = hsum2(a);
        }
        *(float4*)(out + (rowBase + row) * (long)D + ob) =
            make_float4(res[0], res[1], res[2], res[3]);
    }
}

extern "C" void kernel_launch(void* const* d_in, const int* in_sizes, int n_in,
                              void* d_out, int out_size) {
    const float* x = (const float*)d_in[0];   // [16384, 4096]
    const float* A = (const float*)d_in[1];   // [16, 4096]
    const float* B = (const float*)d_in[2];   // [4096, 16]
    float* out = (float*)d_out;               // [16384, 4096]

    cudaFuncSetAttribute(lora_stage1,
                         cudaFuncAttributeMaxDynamicSharedMemorySize, S1_SMEM);
    lora_stage1<<<ROWS_TOTAL / 64, 256, S1_SMEM>>>(x, A);
    dim3 g2(D / 1024, ROWS_TOTAL / 128);
    lora_stage2<<<g2, 256>>>(B, out);
}